// round 2
// baseline (speedup 1.0000x reference)
#include <cuda_runtime.h>
#include <math.h>

// Problem constants: B=8, S=256, N=256, C=64, NH=8, D=2048, 4C=256
// P layout: [b][s][n][ch] = ((b*256+s)*256+n)*256+ch   (134,217,728 floats, 512MB)
//   q  rows n in [0,64):    head h -> n in [h*8, h*8+8)
//   k  rows n in [64,128)
//   vH rows n in [128,192)
//   vV rows n in [192,256)
__device__ float g_P[134217728];
__device__ float g_AH[4194304];   // [b*8+h][s][t]
__device__ float g_AV[4194304];

// ---------------------------------------------------------------------------
// Kernel 1: QKV projection (X(256x64) @ W^T(64x256) + bias) per (b,s) tile,
// fused q/k row-group L2 normalization (groups of 8 n-rows = one head vector).
// grid (2048, 2): blockIdx.x = b*256+s, blockIdx.y = which 128-row half.
// block (32,16) = 512 threads, 8x8 register tile each.
// ---------------------------------------------------------------------------
__global__ void __launch_bounds__(512, 1)
k_qkv(const float* __restrict__ x, const float* __restrict__ w,
      const float* __restrict__ bias)
{
    extern __shared__ float sm[];
    float* Xs = sm;              // [64][129]  transposed X tile (k-major)
    float* Ws = sm + 64 * 129;   // [64][256]  transposed W (k-major)
    __shared__ float snorm[16];

    const int bs   = blockIdx.x;
    const int half = blockIdx.y;
    const int b = bs >> 8, s = bs & 255;
    const int n0 = half << 7;
    const int tx = threadIdx.x, ty = threadIdx.y;
    const int tid = ty * 32 + tx;

    // load X tile (128 rows x 64) transposed into smem
    {
        const float* xg = x + (((size_t)(b * 256 + s) * 256 + n0) * 64);
        int row = tid >> 2;
        int kp  = (tid & 3) << 4;
        const float* src = xg + row * 64 + kp;
        #pragma unroll
        for (int u = 0; u < 16; u += 4) {
            float4 v = *(const float4*)(src + u);
            Xs[(kp + u + 0) * 129 + row] = v.x;
            Xs[(kp + u + 1) * 129 + row] = v.y;
            Xs[(kp + u + 2) * 129 + row] = v.z;
            Xs[(kp + u + 3) * 129 + row] = v.w;
        }
    }
    // load W (256 x 64) transposed into smem: Ws[k][ch]
    {
        int ch = tid >> 1;
        int kp = (tid & 1) << 5;
        const float* src = w + ch * 64 + kp;
        #pragma unroll
        for (int u = 0; u < 32; u += 4) {
            float4 v = *(const float4*)(src + u);
            Ws[(kp + u + 0) * 256 + ch] = v.x;
            Ws[(kp + u + 1) * 256 + ch] = v.y;
            Ws[(kp + u + 2) * 256 + ch] = v.z;
            Ws[(kp + u + 3) * 256 + ch] = v.w;
        }
    }
    __syncthreads();

    float acc[8][8];
    {
        float bj[8];
        #pragma unroll
        for (int j = 0; j < 8; j++) bj[j] = bias[tx * 8 + j];
        #pragma unroll
        for (int i = 0; i < 8; i++)
            #pragma unroll
            for (int j = 0; j < 8; j++) acc[i][j] = bj[j];
    }

    #pragma unroll 4
    for (int k = 0; k < 64; k++) {
        float a[8];
        #pragma unroll
        for (int i = 0; i < 8; i++) a[i] = Xs[k * 129 + ty * 8 + i];
        float4 w0 = *(float4*)(Ws + k * 256 + tx * 8);
        float4 w1 = *(float4*)(Ws + k * 256 + tx * 8 + 4);
        float wv[8] = {w0.x, w0.y, w0.z, w0.w, w1.x, w1.y, w1.z, w1.w};
        #pragma unroll
        for (int i = 0; i < 8; i++)
            #pragma unroll
            for (int j = 0; j < 8; j++)
                acc[i][j] = fmaf(a[i], wv[j], acc[i][j]);
    }

    float scale = 1.0f;
    if (half == 0) {
        // thread ty owns rows ty*8..ty*8+8 == exactly one q/k head vector
        float ss = 0.f;
        #pragma unroll
        for (int i = 0; i < 8; i++)
            #pragma unroll
            for (int j = 0; j < 8; j++) ss += acc[i][j] * acc[i][j];
        #pragma unroll
        for (int off = 16; off > 0; off >>= 1)
            ss += __shfl_xor_sync(0xffffffffu, ss, off);
        if (tx == 0) snorm[ty] = ss;
        __syncthreads();
        float nrm = sqrtf(snorm[ty]);
        scale = 1.0f / fmaxf(nrm, 1e-12f);
    }

    float* og = g_P + ((size_t)(b * 256 + s) * 256 + n0 + ty * 8) * 256 + tx * 8;
    #pragma unroll
    for (int i = 0; i < 8; i++) {
        float4 v0 = make_float4(acc[i][0] * scale, acc[i][1] * scale,
                                acc[i][2] * scale, acc[i][3] * scale);
        float4 v1 = make_float4(acc[i][4] * scale, acc[i][5] * scale,
                                acc[i][6] * scale, acc[i][7] * scale);
        *(float4*)(og + (size_t)i * 256)     = v0;
        *(float4*)(og + (size_t)i * 256 + 4) = v1;
    }
}

// ---------------------------------------------------------------------------
// Kernel 2: sim = Qn @ Kn^T (256x2048 . 2048x256) per (b,h), then dual
// softmax (temperature1 -> A_H, temperature2 -> A_V).
// grid (64, 2): blockIdx.x = b*8+h, blockIdx.y = s-half.
// ---------------------------------------------------------------------------
__global__ void __launch_bounds__(512, 1)
k_attn(const float* __restrict__ t1g, const float* __restrict__ t2g)
{
    __shared__ float Qs[128 * 16];   // [s][dk]
    __shared__ float Ks[16 * 256];   // [dk][t]  (transposed)

    const int bh = blockIdx.x;
    const int b = bh >> 3, h = bh & 7;
    const int s0 = blockIdx.y << 7;
    const int tx = threadIdx.x, ty = threadIdx.y;
    const int tid = ty * 32 + tx;

    const float* qb = g_P + (size_t)b * 16777216 + h * 2048;
    const float* kb = qb + 16384;   // +64 n-rows

    float acc[8][8];
    #pragma unroll
    for (int i = 0; i < 8; i++)
        #pragma unroll
        for (int j = 0; j < 8; j++) acc[i][j] = 0.f;

    for (int d0 = 0; d0 < 2048; d0 += 16) {
        {
            int sr = tid >> 2;
            int kp = (tid & 3) << 2;
            float4 v = *(const float4*)(qb + (size_t)(s0 + sr) * 65536 + d0 + kp);
            *(float4*)(Qs + sr * 16 + kp) = v;
        }
        {
            int t  = tid >> 1;
            int kp = (tid & 1) << 3;
            const float* src = kb + (size_t)t * 65536 + d0 + kp;
            float4 v0 = *(const float4*)(src);
            float4 v1 = *(const float4*)(src + 4);
            Ks[(kp + 0) * 256 + t] = v0.x;
            Ks[(kp + 1) * 256 + t] = v0.y;
            Ks[(kp + 2) * 256 + t] = v0.z;
            Ks[(kp + 3) * 256 + t] = v0.w;
            Ks[(kp + 4) * 256 + t] = v1.x;
            Ks[(kp + 5) * 256 + t] = v1.y;
            Ks[(kp + 6) * 256 + t] = v1.z;
            Ks[(kp + 7) * 256 + t] = v1.w;
        }
        __syncthreads();
        #pragma unroll
        for (int kk = 0; kk < 16; kk++) {
            float a[8];
            #pragma unroll
            for (int i = 0; i < 8; i++) a[i] = Qs[(ty * 8 + i) * 16 + kk];
            float4 k0 = *(float4*)(Ks + kk * 256 + tx * 8);
            float4 k1 = *(float4*)(Ks + kk * 256 + tx * 8 + 4);
            float kv[8] = {k0.x, k0.y, k0.z, k0.w, k1.x, k1.y, k1.z, k1.w};
            #pragma unroll
            for (int i = 0; i < 8; i++)
                #pragma unroll
                for (int j = 0; j < 8; j++)
                    acc[i][j] = fmaf(a[i], kv[j], acc[i][j]);
        }
        __syncthreads();
    }

    const float t1 = t1g[h];
    const float t2 = t2g[h];
    float* AH = g_AH + (size_t)bh * 65536;
    float* AV = g_AV + (size_t)bh * 65536;

    #pragma unroll
    for (int i = 0; i < 8; i++) {
        const int srow = s0 + ty * 8 + i;
        // ---- softmax H ----
        {
            float mx = -3.0e38f;
            #pragma unroll
            for (int j = 0; j < 8; j++) mx = fmaxf(mx, acc[i][j] * t1);
            #pragma unroll
            for (int off = 16; off > 0; off >>= 1)
                mx = fmaxf(mx, __shfl_xor_sync(0xffffffffu, mx, off));
            float e[8]; float sum = 0.f;
            #pragma unroll
            for (int j = 0; j < 8; j++) { e[j] = __expf(acc[i][j] * t1 - mx); sum += e[j]; }
            #pragma unroll
            for (int off = 16; off > 0; off >>= 1)
                sum += __shfl_xor_sync(0xffffffffu, sum, off);
            float inv = 1.0f / sum;
            float* dst = AH + (size_t)srow * 256 + tx * 8;
            *(float4*)(dst)     = make_float4(e[0]*inv, e[1]*inv, e[2]*inv, e[3]*inv);
            *(float4*)(dst + 4) = make_float4(e[4]*inv, e[5]*inv, e[6]*inv, e[7]*inv);
        }
        // ---- softmax V ----
        {
            float mx = -3.0e38f;
            #pragma unroll
            for (int j = 0; j < 8; j++) mx = fmaxf(mx, acc[i][j] * t2);
            #pragma unroll
            for (int off = 16; off > 0; off >>= 1)
                mx = fmaxf(mx, __shfl_xor_sync(0xffffffffu, mx, off));
            float e[8]; float sum = 0.f;
            #pragma unroll
            for (int j = 0; j < 8; j++) { e[j] = __expf(acc[i][j] * t2 - mx); sum += e[j]; }
            #pragma unroll
            for (int off = 16; off > 0; off >>= 1)
                sum += __shfl_xor_sync(0xffffffffu, sum, off);
            float inv = 1.0f / sum;
            float* dst = AV + (size_t)srow * 256 + tx * 8;
            *(float4*)(dst)     = make_float4(e[0]*inv, e[1]*inv, e[2]*inv, e[3]*inv);
            *(float4*)(dst + 4) = make_float4(e[4]*inv, e[5]*inv, e[6]*inv, e[7]*inv);
        }
    }
}

// ---------------------------------------------------------------------------
// Kernel 3: xsum = A_H @ V_H + A_V @ V_Vfinal  (per (b,h), 256x2048),
// fused 64->64 output projection epilogue, writes d_out directly.
// grid (64, 16): blockIdx.x = b*8+h; blockIdx.y: bit0 = s-half, bits[1..3] =
// d-group (256 d-cols = 4 output n-rows "j").
// ---------------------------------------------------------------------------
__global__ void __launch_bounds__(512, 1)
k_av(const float* __restrict__ pw, const float* __restrict__ pb,
     float* __restrict__ out)
{
    extern __shared__ float sm[];
    float* AHs = sm;          // [128][16]
    float* AVs = sm + 2048;   // [128][16]
    float* Vhs = sm + 4096;   // [16][256]
    float* Vvs = sm + 8192;   // [16][256]

    const int bh = blockIdx.x;
    const int b = bh >> 3, h = bh & 7;
    const int tile = blockIdx.y;
    const int s0 = (tile & 1) << 7;
    const int dg = tile >> 1;        // 0..7
    const int d0 = dg << 8;          // d offset within head (0..2048)
    const int j0 = dg << 2;          // output n-row group base (within head)

    const int tx = threadIdx.x, ty = threadIdx.y;
    const int tid = ty * 32 + tx;

    const float* AHb = g_AH + (size_t)bh * 65536 + (size_t)s0 * 256;
    const float* AVb = g_AV + (size_t)bh * 65536 + (size_t)s0 * 256;
    // V_H[t, d] = P[b, t, 128 + h*8 + d/256, d%256]  (contiguous 2048/row)
    const float* vh = g_P + (size_t)b * 16777216 + 32768 + h * 2048 + d0;
    // V_Vfinal[t, j*64+c] = P[b, h*32+j, 192 + t/4, (t%4)*64 + c]
    const float* vv = g_P + (size_t)b * 16777216 + (size_t)(h * 32 + j0) * 65536 + 49152;

    float acc[8][8];
    #pragma unroll
    for (int i = 0; i < 8; i++)
        #pragma unroll
        for (int j = 0; j < 8; j++) acc[i][j] = 0.f;

    for (int t0 = 0; t0 < 256; t0 += 16) {
        {
            int sr = tid >> 2;
            int tp = (tid & 3) << 2;
            *(float4*)(AHs + sr * 16 + tp) =
                *(const float4*)(AHb + (size_t)sr * 256 + t0 + tp);
            *(float4*)(AVs + sr * 16 + tp) =
                *(const float4*)(AVb + (size_t)sr * 256 + t0 + tp);
        }
        {
            int tt = tid >> 5;
            int dp = (tid & 31) << 3;
            const float* src = vh + (size_t)(t0 + tt) * 65536 + dp;
            *(float4*)(Vhs + tt * 256 + dp)     = *(const float4*)(src);
            *(float4*)(Vhs + tt * 256 + dp + 4) = *(const float4*)(src + 4);
            int jj = dp >> 6, c = dp & 63;
            const float* src2 = vv + (size_t)jj * 65536 + (t0 + tt) * 64 + c;
            *(float4*)(Vvs + tt * 256 + dp)     = *(const float4*)(src2);
            *(float4*)(Vvs + tt * 256 + dp + 4) = *(const float4*)(src2 + 4);
        }
        __syncthreads();
        #pragma unroll
        for (int tt = 0; tt < 16; tt++) {
            float a1[8], a2[8];
            #pragma unroll
            for (int i = 0; i < 8; i++) {
                a1[i] = AHs[(ty * 8 + i) * 16 + tt];
                a2[i] = AVs[(ty * 8 + i) * 16 + tt];
            }
            float4 u0 = *(float4*)(Vhs + tt * 256 + tx * 8);
            float4 u1 = *(float4*)(Vhs + tt * 256 + tx * 8 + 4);
            float4 w0 = *(float4*)(Vvs + tt * 256 + tx * 8);
            float4 w1 = *(float4*)(Vvs + tt * 256 + tx * 8 + 4);
            float v1[8] = {u0.x, u0.y, u0.z, u0.w, u1.x, u1.y, u1.z, u1.w};
            float v2[8] = {w0.x, w0.y, w0.z, w0.w, w1.x, w1.y, w1.z, w1.w};
            #pragma unroll
            for (int i = 0; i < 8; i++)
                #pragma unroll
                for (int j = 0; j < 8; j++) {
                    acc[i][j] = fmaf(a1[i], v1[j], acc[i][j]);
                    acc[i][j] = fmaf(a2[i], v2[j], acc[i][j]);
                }
        }
        __syncthreads();
    }

    // ---------------- fused projection epilogue ----------------
    float* xs  = sm;                 // [128][256]   xsum
    float* pwt = sm + 32768;         // [64][64]     proj_w transposed [c'][c_out]
    float* pbs = sm + 32768 + 4096;  // [64]

    #pragma unroll
    for (int i = 0; i < 8; i++) {
        *(float4*)(xs + (ty * 8 + i) * 256 + tx * 8) =
            make_float4(acc[i][0], acc[i][1], acc[i][2], acc[i][3]);
        *(float4*)(xs + (ty * 8 + i) * 256 + tx * 8 + 4) =
            make_float4(acc[i][4], acc[i][5], acc[i][6], acc[i][7]);
    }
    if (tid < 64) pbs[tid] = pb[tid];
    {
        int co = tid >> 3;
        int cp = (tid & 7) << 3;
        const float* src = pw + co * 64 + cp;
        float4 v0 = *(const float4*)(src);
        float4 v1 = *(const float4*)(src + 4);
        pwt[(cp + 0) * 64 + co] = v0.x;
        pwt[(cp + 1) * 64 + co] = v0.y;
        pwt[(cp + 2) * 64 + co] = v0.z;
        pwt[(cp + 3) * 64 + co] = v0.w;
        pwt[(cp + 4) * 64 + co] = v1.x;
        pwt[(cp + 5) * 64 + co] = v1.y;
        pwt[(cp + 6) * 64 + co] = v1.z;
        pwt[(cp + 7) * 64 + co] = v1.w;
    }
    __syncthreads();

    const int jl  = tx >> 3;         // local j within the 4-j group
    const int co0 = (tx & 7) << 3;   // c_out base
    float acc2[8][8];
    #pragma unroll
    for (int i = 0; i < 8; i++)
        #pragma unroll
        for (int jc = 0; jc < 8; jc++) acc2[i][jc] = pbs[co0 + jc];

    #pragma unroll 4
    for (int cp = 0; cp < 64; cp++) {
        float xv[8];
        #pragma unroll
        for (int i = 0; i < 8; i++) xv[i] = xs[(ty * 8 + i) * 256 + jl * 64 + cp];
        float4 w0 = *(float4*)(pwt + cp * 64 + co0);
        float4 w1 = *(float4*)(pwt + cp * 64 + co0 + 4);
        float wv[8] = {w0.x, w0.y, w0.z, w0.w, w1.x, w1.y, w1.z, w1.w};
        #pragma unroll
        for (int i = 0; i < 8; i++)
            #pragma unroll
            for (int jc = 0; jc < 8; jc++)
                acc2[i][jc] = fmaf(xv[i], wv[jc], acc2[i][jc]);
    }

    #pragma unroll
    for (int i = 0; i < 8; i++) {
        float* og = out + ((size_t)(b * 256 + s0 + ty * 8 + i) * 256
                           + h * 32 + j0 + jl) * 64 + co0;
        *(float4*)(og)     = make_float4(acc2[i][0], acc2[i][1], acc2[i][2], acc2[i][3]);
        *(float4*)(og + 4) = make_float4(acc2[i][4], acc2[i][5], acc2[i][6], acc2[i][7]);
    }
}

// ---------------------------------------------------------------------------
extern "C" void kernel_launch(void* const* d_in, const int* in_sizes, int n_in,
                              void* d_out, int out_size)
{
    const float* x      = (const float*)d_in[0];
    const float* qkv_w  = (const float*)d_in[1];
    const float* qkv_b  = (const float*)d_in[2];
    const float* proj_w = (const float*)d_in[3];
    const float* proj_b = (const float*)d_in[4];
    const float* t1     = (const float*)d_in[5];
    const float* t2     = (const float*)d_in[6];
    float* out = (float*)d_out;

    const int smem1 = (64 * 129 + 64 * 256) * (int)sizeof(float);          // ~96.3 KB
    const int smem3 = (32768 + 4096 + 64) * (int)sizeof(float);            // ~144.3 KB

    cudaFuncSetAttribute((const void*)k_qkv,
                         cudaFuncAttributeMaxDynamicSharedMemorySize, smem1);
    cudaFuncSetAttribute((const void*)k_av,
                         cudaFuncAttributeMaxDynamicSharedMemorySize, smem3);

    dim3 blk(32, 16);
    k_qkv<<<dim3(2048, 2), blk, smem1>>>(x, qkv_w, qkv_b);
    k_attn<<<dim3(64, 2), blk>>>(t1, t2);
    k_av<<<dim3(64, 16), blk, smem3>>>(proj_w, proj_b, out);
}

// round 3
// speedup vs baseline: 4.5077x; 4.5077x over previous
#include <cuda_runtime.h>
#include <cuda_fp16.h>
#include <math.h>
#include <stdint.h>

// B=8, S=256, N=256, C=64, NH=8, D=2048
// P (fp16): flat ((b*256+s)*256+n)*256+c4 ; n:[0,64)=q(norm) [64,128)=k(norm)
// [128,192)=vH [192,256)=vV
__device__ __half g_Ph[134217728];
__device__ __half g_AHm[4194304];   // [bh][s][t]
__device__ __half g_AVm[4194304];

#define DINL __device__ __forceinline__

DINL uint32_t su32(const void* p) { return (uint32_t)__cvta_generic_to_shared(p); }

DINL void ldsm4(uint32_t r[4], const void* p) {
    asm volatile("ldmatrix.sync.aligned.m8n8.x4.shared.b16 {%0,%1,%2,%3},[%4];"
        : "=r"(r[0]), "=r"(r[1]), "=r"(r[2]), "=r"(r[3]) : "r"(su32(p)));
}
DINL void ldsm4t(uint32_t r[4], const void* p) {
    asm volatile("ldmatrix.sync.aligned.m8n8.x4.trans.shared.b16 {%0,%1,%2,%3},[%4];"
        : "=r"(r[0]), "=r"(r[1]), "=r"(r[2]), "=r"(r[3]) : "r"(su32(p)));
}
DINL void mma8(float c[4], const uint32_t a[4], uint32_t b0, uint32_t b1) {
    asm volatile("mma.sync.aligned.m16n8k16.row.col.f32.f16.f16.f32 "
        "{%0,%1,%2,%3},{%4,%5,%6,%7},{%8,%9},{%0,%1,%2,%3};"
        : "+f"(c[0]), "+f"(c[1]), "+f"(c[2]), "+f"(c[3])
        : "r"(a[0]), "r"(a[1]), "r"(a[2]), "r"(a[3]), "r"(b0), "r"(b1));
}
DINL void cpa16(void* s, const void* g) {
    asm volatile("cp.async.cg.shared.global [%0], [%1], 16;" :: "r"(su32(s)), "l"(g));
}
DINL void cpcommit() { asm volatile("cp.async.commit_group;"); }
DINL void cpwait0()  { asm volatile("cp.async.wait_group 0;"); }
DINL void cpwait1()  { asm volatile("cp.async.wait_group 1;"); }

// ---------------------------------------------------------------------------
// Kernel 1: P = X @ W^T + bias (per (b,s): 256x256, K=64), fused q/k 8-row-
// group L2 norm. grid(2048,2): x=b*256+s, y=128-row half. 512 thr = 16 warps
// (4x4), warp tile 32x64.
// ---------------------------------------------------------------------------
__global__ void __launch_bounds__(512, 1)
k_qkv(const float* __restrict__ x, const float* __restrict__ w,
      const float* __restrict__ bias_)
{
    extern __shared__ __half sm[];
    __half* Xs = sm;                       // [128][72]
    __half* Ws = sm + 128 * 72;            // [256][72]
    float*  bsh = (float*)(Ws + 256 * 72); // [256]
    float*  gss = bsh + 256;               // [16]

    const int bs = blockIdx.x, half_ = blockIdx.y, n0 = half_ << 7;
    const int tid = threadIdx.x, lane = tid & 31, warp = tid >> 5;
    const int wr = warp >> 2, wc = warp & 3;

    { // X tile (128 x 64 fp32) -> fp16 smem
        int row = tid >> 2, k0 = (tid & 3) << 4;
        const float* src = x + ((size_t)bs * 256 + n0 + row) * 64 + k0;
        __half* dst = Xs + row * 72 + k0;
        #pragma unroll
        for (int i = 0; i < 4; i++) {
            float4 v = *(const float4*)(src + i * 4);
            dst[i*4+0] = __float2half_rn(v.x); dst[i*4+1] = __float2half_rn(v.y);
            dst[i*4+2] = __float2half_rn(v.z); dst[i*4+3] = __float2half_rn(v.w);
        }
    }
    { // W (256 x 64 fp32) -> fp16 smem [o][k]
        int row = tid >> 1, k0 = (tid & 1) << 5;
        const float* src = w + row * 64 + k0;
        __half* dst = Ws + row * 72 + k0;
        #pragma unroll
        for (int i = 0; i < 8; i++) {
            float4 v = *(const float4*)(src + i * 4);
            dst[i*4+0] = __float2half_rn(v.x); dst[i*4+1] = __float2half_rn(v.y);
            dst[i*4+2] = __float2half_rn(v.z); dst[i*4+3] = __float2half_rn(v.w);
        }
    }
    if (tid < 256) bsh[tid] = bias_[tid];
    if (tid < 16)  gss[tid] = 0.f;
    __syncthreads();

    float acc[2][8][4];
    #pragma unroll
    for (int mt = 0; mt < 2; mt++)
        #pragma unroll
        for (int nt = 0; nt < 8; nt++)
            #pragma unroll
            for (int q = 0; q < 4; q++) acc[mt][nt][q] = 0.f;

    #pragma unroll
    for (int kk = 0; kk < 4; kk++) {
        uint32_t af[2][4];
        #pragma unroll
        for (int mt = 0; mt < 2; mt++)
            ldsm4(af[mt], Xs + (wr*32 + mt*16 + (lane & 15)) * 72
                             + kk*16 + ((lane >> 4) << 3));
        #pragma unroll
        for (int g = 0; g < 4; g++) {
            uint32_t r[4];
            ldsm4(r, Ws + (wc*64 + g*16 + (lane & 15)) * 72
                        + kk*16 + ((lane >> 4) << 3));
            #pragma unroll
            for (int mt = 0; mt < 2; mt++) {
                mma8(acc[mt][2*g],   af[mt], r[0], r[2]);
                mma8(acc[mt][2*g+1], af[mt], r[1], r[3]);
            }
        }
    }

    // add bias (before norm)
    #pragma unroll
    for (int nt = 0; nt < 8; nt++) {
        float b0 = bsh[wc*64 + nt*8 + 2*(lane & 3)];
        float b1 = bsh[wc*64 + nt*8 + 2*(lane & 3) + 1];
        #pragma unroll
        for (int mt = 0; mt < 2; mt++) {
            acc[mt][nt][0] += b0; acc[mt][nt][1] += b1;
            acc[mt][nt][2] += b0; acc[mt][nt][3] += b1;
        }
    }

    // q/k norms: rows n<128 == half 0. 8-row groups; full warp covers one
    // group per (mt, rowhalf).
    if (half_ == 0) {
        #pragma unroll
        for (int mt = 0; mt < 2; mt++) {
            float p01 = 0.f, p23 = 0.f;
            #pragma unroll
            for (int nt = 0; nt < 8; nt++) {
                p01 += acc[mt][nt][0]*acc[mt][nt][0] + acc[mt][nt][1]*acc[mt][nt][1];
                p23 += acc[mt][nt][2]*acc[mt][nt][2] + acc[mt][nt][3]*acc[mt][nt][3];
            }
            #pragma unroll
            for (int off = 16; off > 0; off >>= 1) {
                p01 += __shfl_xor_sync(0xffffffffu, p01, off);
                p23 += __shfl_xor_sync(0xffffffffu, p23, off);
            }
            if (lane == 0) {
                atomicAdd(&gss[wr*4 + mt*2],     p01);
                atomicAdd(&gss[wr*4 + mt*2 + 1], p23);
            }
        }
    }
    __syncthreads();

    #pragma unroll
    for (int mt = 0; mt < 2; mt++) {
        float s01 = 1.f, s23 = 1.f;
        if (half_ == 0) {
            s01 = 1.f / fmaxf(sqrtf(gss[wr*4 + mt*2]),     1e-12f);
            s23 = 1.f / fmaxf(sqrtf(gss[wr*4 + mt*2 + 1]), 1e-12f);
        }
        int r0 = n0 + wr*32 + mt*16 + (lane >> 2);
        #pragma unroll
        for (int nt = 0; nt < 8; nt++) {
            int col = wc*64 + nt*8 + 2*(lane & 3);
            __half* p0 = g_Ph + ((size_t)bs * 256 + r0) * 256 + col;
            *(__half2*)p0 = __floats2half2_rn(acc[mt][nt][0]*s01, acc[mt][nt][1]*s01);
            *(__half2*)(p0 + 8*256) =
                __floats2half2_rn(acc[mt][nt][2]*s23, acc[mt][nt][3]*s23);
        }
    }
}

// ---------------------------------------------------------------------------
// Kernel 2: sim = Qn @ Kn^T per (b,h) + dual softmax (no max-shift; |sim|<=1).
// grid(64,2): bh, s-half. 512 thr, warp tile 32x64 over 128x256.
// K=2048, chunk 64, cp.async double buffered.
// ---------------------------------------------------------------------------
__global__ void __launch_bounds__(512, 1)
k_attn(const float* __restrict__ t1g, const float* __restrict__ t2g)
{
    extern __shared__ __half sm2[];
    __half* Qs = sm2;                       // 2 x [128][88]
    __half* Ks = sm2 + 2 * 128 * 88;        // 2 x [256][88]
    float*  rs1 = (float*)(Ks + 2 * 256 * 88); // [128]
    float*  rs2 = rs1 + 128;                   // [128]

    const int bh = blockIdx.x, s0 = blockIdx.y << 7;
    const int b = bh >> 3, h = bh & 7;
    const __half* qb = g_Ph + (size_t)b * 16777216 + h * 2048;
    const __half* kb = qb + 16384;

    const int tid = threadIdx.x, lane = tid & 31, warp = tid >> 5;
    const int wr = warp >> 2, wc = warp & 3;

    if (tid < 128) { rs1[tid] = 0.f; rs2[tid] = 0.f; }

    auto loadQ = [&](int buf, int c) {
        int d0 = c * 64;
        #pragma unroll
        for (int i = 0; i < 2; i++) {
            int seg = tid * 2 + i, row = seg >> 3, off = (seg & 7) << 3;
            cpa16(Qs + buf*11264 + row*88 + off,
                  qb + (size_t)(s0 + row) * 65536 + d0 + off);
        }
    };
    auto loadK = [&](int buf, int c) {
        int d0 = c * 64;
        #pragma unroll
        for (int i = 0; i < 4; i++) {
            int seg = tid * 4 + i, row = seg >> 3, off = (seg & 7) << 3;
            cpa16(Ks + buf*22528 + row*88 + off,
                  kb + (size_t)row * 65536 + d0 + off);
        }
    };

    float acc[2][8][4];
    #pragma unroll
    for (int mt = 0; mt < 2; mt++)
        #pragma unroll
        for (int nt = 0; nt < 8; nt++)
            #pragma unroll
            for (int q = 0; q < 4; q++) acc[mt][nt][q] = 0.f;

    loadQ(0, 0); loadK(0, 0); cpcommit();
    for (int c = 0; c < 32; c++) {
        if (c < 31) { loadQ((c+1)&1, c+1); loadK((c+1)&1, c+1); cpcommit(); cpwait1(); }
        else cpwait0();
        __syncthreads();
        const __half* Q = Qs + (c & 1) * 11264;
        const __half* K = Ks + (c & 1) * 22528;
        #pragma unroll
        for (int kk = 0; kk < 4; kk++) {
            uint32_t af[2][4];
            #pragma unroll
            for (int mt = 0; mt < 2; mt++)
                ldsm4(af[mt], Q + (wr*32 + mt*16 + (lane & 15)) * 88
                                + kk*16 + ((lane >> 4) << 3));
            #pragma unroll
            for (int g = 0; g < 4; g++) {
                uint32_t r[4];
                ldsm4(r, K + (wc*64 + g*16 + (lane & 15)) * 88
                           + kk*16 + ((lane >> 4) << 3));
                #pragma unroll
                for (int mt = 0; mt < 2; mt++) {
                    mma8(acc[mt][2*g],   af[mt], r[0], r[2]);
                    mma8(acc[mt][2*g+1], af[mt], r[1], r[3]);
                }
            }
        }
        __syncthreads();
    }

    const float t1 = t1g[h], t2 = t2g[h];

    // pass 1: row sums of exp
    #pragma unroll
    for (int mt = 0; mt < 2; mt++) {
        float p1a = 0.f, p1b = 0.f, p2a = 0.f, p2b = 0.f;
        #pragma unroll
        for (int nt = 0; nt < 8; nt++) {
            p1a += __expf(acc[mt][nt][0]*t1) + __expf(acc[mt][nt][1]*t1);
            p1b += __expf(acc[mt][nt][2]*t1) + __expf(acc[mt][nt][3]*t1);
            p2a += __expf(acc[mt][nt][0]*t2) + __expf(acc[mt][nt][1]*t2);
            p2b += __expf(acc[mt][nt][2]*t2) + __expf(acc[mt][nt][3]*t2);
        }
        #pragma unroll
        for (int off = 1; off < 4; off <<= 1) {
            p1a += __shfl_xor_sync(0xffffffffu, p1a, off);
            p1b += __shfl_xor_sync(0xffffffffu, p1b, off);
            p2a += __shfl_xor_sync(0xffffffffu, p2a, off);
            p2b += __shfl_xor_sync(0xffffffffu, p2b, off);
        }
        if ((lane & 3) == 0) {
            int r0 = wr*32 + mt*16 + (lane >> 2);
            atomicAdd(&rs1[r0], p1a);     atomicAdd(&rs1[r0 + 8], p1b);
            atomicAdd(&rs2[r0], p2a);     atomicAdd(&rs2[r0 + 8], p2b);
        }
    }
    __syncthreads();

    // pass 2: normalize + store fp16
    #pragma unroll
    for (int mt = 0; mt < 2; mt++) {
        int r0 = wr*32 + mt*16 + (lane >> 2);
        float i1a = 1.f / rs1[r0], i1b = 1.f / rs1[r0 + 8];
        float i2a = 1.f / rs2[r0], i2b = 1.f / rs2[r0 + 8];
        #pragma unroll
        for (int nt = 0; nt < 8; nt++) {
            int col = wc*64 + nt*8 + 2*(lane & 3);
            size_t base = (size_t)bh * 65536 + (size_t)(s0 + r0) * 256 + col;
            *(__half2*)(g_AHm + base) = __floats2half2_rn(
                __expf(acc[mt][nt][0]*t1)*i1a, __expf(acc[mt][nt][1]*t1)*i1a);
            *(__half2*)(g_AHm + base + 2048) = __floats2half2_rn(
                __expf(acc[mt][nt][2]*t1)*i1b, __expf(acc[mt][nt][3]*t1)*i1b);
            *(__half2*)(g_AVm + base) = __floats2half2_rn(
                __expf(acc[mt][nt][0]*t2)*i2a, __expf(acc[mt][nt][1]*t2)*i2a);
            *(__half2*)(g_AVm + base + 2048) = __floats2half2_rn(
                __expf(acc[mt][nt][2]*t2)*i2b, __expf(acc[mt][nt][3]*t2)*i2b);
        }
    }
}

// ---------------------------------------------------------------------------
// Kernel 3: xsum = A_H@V_H + A_V@V_Vfinal per (b,h) [128s x 256d block],
// fused proj MMA epilogue -> out. grid(64,16), 512 thr, warp 32x64.
// K=256 (t), chunk 32, cp.async double buffered. V via ldmatrix.trans.
// ---------------------------------------------------------------------------
__global__ void __launch_bounds__(512, 1)
k_av(const float* __restrict__ pw, const float* __restrict__ pb,
     float* __restrict__ out)
{
    extern __shared__ __half sm3[];
    __half* AHs = sm3;                   // 2 x [128][40]
    __half* AVs = AHs + 2 * 5120;        // 2 x [128][40]
    __half* Vhs = AVs + 2 * 5120;        // 2 x [32][264]
    __half* Vvs = Vhs + 2 * 8448;        // 2 x [32][264]
    __half* PWs = Vvs + 2 * 8448;        // [64][72]
    float*  pbs = (float*)(PWs + 64 * 72); // [64]
    __half* XSs = sm3;                   // reuse: [128][264] (33792 < 54272)

    const int bh = blockIdx.x, b = bh >> 3, h = bh & 7;
    const int tile = blockIdx.y;
    const int s0 = (tile & 1) << 7, dg = tile >> 1;
    const int d0 = dg << 8, j0 = dg << 2;

    const int tid = threadIdx.x, lane = tid & 31, warp = tid >> 5;
    const int wr = warp >> 2, wc = warp & 3;

    const __half* AHg = g_AHm + (size_t)bh * 65536 + (size_t)s0 * 256;
    const __half* AVg = g_AVm + (size_t)bh * 65536 + (size_t)s0 * 256;
    const __half* vh  = g_Ph + (size_t)b * 16777216 + 32768 + h * 2048 + d0;
    const __half* vv  = g_Ph + (size_t)b * 16777216 + (size_t)(h*32 + j0) * 65536 + 49152;

    { // proj weight [co][c'] -> fp16 smem
        int row = tid >> 3, k0 = (tid & 7) << 3;
        const float* src = pw + row * 64 + k0;
        __half* dst = PWs + row * 72 + k0;
        #pragma unroll
        for (int i = 0; i < 2; i++) {
            float4 v = *(const float4*)(src + i * 4);
            dst[i*4+0] = __float2half_rn(v.x); dst[i*4+1] = __float2half_rn(v.y);
            dst[i*4+2] = __float2half_rn(v.z); dst[i*4+3] = __float2half_rn(v.w);
        }
    }
    if (tid < 64) pbs[tid] = pb[tid];

    auto loadA = [&](int buf, int c) {
        int t0 = c * 32;
        int row = tid >> 2, off = (tid & 3) << 3;
        cpa16(AHs + buf*5120 + row*40 + off, AHg + (size_t)row * 256 + t0 + off);
        cpa16(AVs + buf*5120 + row*40 + off, AVg + (size_t)row * 256 + t0 + off);
    };
    auto loadV = [&](int buf, int c) {
        int t0 = c * 32;
        #pragma unroll
        for (int i = 0; i < 2; i++) {
            int sg = tid * 2 + i, row = sg >> 5, off = (sg & 31) << 3;
            cpa16(Vhs + buf*8448 + row*264 + off,
                  vh + (size_t)(t0 + row) * 65536 + off);
            int jj = off >> 6, cc = off & 63;
            cpa16(Vvs + buf*8448 + row*264 + off,
                  vv + (size_t)jj * 65536 + (t0 + row) * 64 + cc);
        }
    };

    float acc[2][8][4];
    #pragma unroll
    for (int mt = 0; mt < 2; mt++)
        #pragma unroll
        for (int nt = 0; nt < 8; nt++)
            #pragma unroll
            for (int q = 0; q < 4; q++) acc[mt][nt][q] = 0.f;

    loadA(0, 0); loadV(0, 0); cpcommit();
    for (int c = 0; c < 8; c++) {
        if (c < 7) { loadA((c+1)&1, c+1); loadV((c+1)&1, c+1); cpcommit(); cpwait1(); }
        else cpwait0();
        __syncthreads();
        const __half* AH = AHs + (c & 1) * 5120;
        const __half* AV = AVs + (c & 1) * 5120;
        const __half* VH = Vhs + (c & 1) * 8448;
        const __half* VV = Vvs + (c & 1) * 8448;
        #pragma unroll
        for (int kk = 0; kk < 2; kk++) {
            uint32_t aH[2][4], aV[2][4];
            #pragma unroll
            for (int mt = 0; mt < 2; mt++) {
                ldsm4(aH[mt], AH + (wr*32 + mt*16 + (lane & 15)) * 40
                                 + kk*16 + ((lane >> 4) << 3));
                ldsm4(aV[mt], AV + (wr*32 + mt*16 + (lane & 15)) * 40
                                 + kk*16 + ((lane >> 4) << 3));
            }
            #pragma unroll
            for (int g = 0; g < 4; g++) {
                int D0 = wc*64 + g*16;
                int trow = kk*16 + ((lane >> 4) << 3) + (lane & 7);
                int dcol = D0 + (((lane >> 3) & 1) << 3);
                uint32_t r[4];
                ldsm4t(r, VH + trow*264 + dcol);
                #pragma unroll
                for (int mt = 0; mt < 2; mt++) {
                    mma8(acc[mt][2*g],   aH[mt], r[0], r[2]);
                    mma8(acc[mt][2*g+1], aH[mt], r[1], r[3]);
                }
                ldsm4t(r, VV + trow*264 + dcol);
                #pragma unroll
                for (int mt = 0; mt < 2; mt++) {
                    mma8(acc[mt][2*g],   aV[mt], r[0], r[2]);
                    mma8(acc[mt][2*g+1], aV[mt], r[1], r[3]);
                }
            }
        }
        __syncthreads();
    }

    // stage xsum (fp16) into smem, then proj MMA
    __syncthreads();
    #pragma unroll
    for (int mt = 0; mt < 2; mt++) {
        int r0 = wr*32 + mt*16 + (lane >> 2);
        #pragma unroll
        for (int nt = 0; nt < 8; nt++) {
            int col = wc*64 + nt*8 + 2*(lane & 3);
            *(__half2*)(XSs + r0*264 + col) =
                __floats2half2_rn(acc[mt][nt][0], acc[mt][nt][1]);
            *(__half2*)(XSs + (r0+8)*264 + col) =
                __floats2half2_rn(acc[mt][nt][2], acc[mt][nt][3]);
        }
    }
    __syncthreads();

    float a2[2][8][4];
    #pragma unroll
    for (int mt = 0; mt < 2; mt++)
        #pragma unroll
        for (int nt = 0; nt < 8; nt++)
            #pragma unroll
            for (int q = 0; q < 4; q++) a2[mt][nt][q] = 0.f;

    #pragma unroll
    for (int kk = 0; kk < 4; kk++) {
        uint32_t af[2][4];
        #pragma unroll
        for (int mt = 0; mt < 2; mt++)
            ldsm4(af[mt], XSs + (wr*32 + mt*16 + (lane & 15)) * 264
                              + wc*64 + kk*16 + ((lane >> 4) << 3));
        #pragma unroll
        for (int g = 0; g < 4; g++) {
            uint32_t r[4];
            ldsm4(r, PWs + (g*16 + (lane & 15)) * 72
                         + kk*16 + ((lane >> 4) << 3));
            #pragma unroll
            for (int mt = 0; mt < 2; mt++) {
                mma8(a2[mt][2*g],   af[mt], r[0], r[2]);
                mma8(a2[mt][2*g+1], af[mt], r[1], r[3]);
            }
        }
    }

    #pragma unroll
    for (int mt = 0; mt < 2; mt++) {
        int r0 = wr*32 + mt*16 + (lane >> 2);
        #pragma unroll
        for (int nt = 0; nt < 8; nt++) {
            int co = nt*8 + 2*(lane & 3);
            float b0 = pbs[co], b1 = pbs[co + 1];
            float* o0 = out + ((size_t)(b*256 + s0 + r0) * 256 + h*32 + j0 + wc) * 64 + co;
            float* o1 = out + ((size_t)(b*256 + s0 + r0 + 8) * 256 + h*32 + j0 + wc) * 64 + co;
            *(float2*)o0 = make_float2(a2[mt][nt][0] + b0, a2[mt][nt][1] + b1);
            *(float2*)o1 = make_float2(a2[mt][nt][2] + b0, a2[mt][nt][3] + b1);
        }
    }
}

// ---------------------------------------------------------------------------
extern "C" void kernel_launch(void* const* d_in, const int* in_sizes, int n_in,
                              void* d_out, int out_size)
{
    const float* x      = (const float*)d_in[0];
    const float* qkv_w  = (const float*)d_in[1];
    const float* qkv_b  = (const float*)d_in[2];
    const float* proj_w = (const float*)d_in[3];
    const float* proj_b = (const float*)d_in[4];
    const float* t1     = (const float*)d_in[5];
    const float* t2     = (const float*)d_in[6];
    float* out = (float*)d_out;

    const int smem1 = (128*72 + 256*72) * 2 + (256 + 16) * 4;          // ~56.4 KB
    const int smem2 = (2*128*88 + 2*256*88) * 2 + 256 * 4;             // ~136.2 KB
    const int smem3 = (2*5120*2 + 2*8448*2 + 64*72) * 2 + 64 * 4;      // ~118.0 KB

    static int inited = 0;
    cudaFuncSetAttribute((const void*)k_qkv,
                         cudaFuncAttributeMaxDynamicSharedMemorySize, smem1);
    cudaFuncSetAttribute((const void*)k_attn,
                         cudaFuncAttributeMaxDynamicSharedMemorySize, smem2);
    cudaFuncSetAttribute((const void*)k_av,
                         cudaFuncAttributeMaxDynamicSharedMemorySize, smem3);
    (void)inited;

    k_qkv <<<dim3(2048, 2), 512, smem1>>>(x, qkv_w, qkv_b);
    k_attn<<<dim3(64, 2),   512, smem2>>>(t1, t2);
    k_av  <<<dim3(64, 16),  512, smem3>>>(proj_w, proj_b, out);
}

// round 4
// speedup vs baseline: 4.9816x; 1.1051x over previous
#include <cuda_runtime.h>
#include <cuda_fp16.h>
#include <math.h>
#include <stdint.h>

// B=8, S=256, N=256, C=64, NH=8, D=2048
// P (fp16): flat ((b*256+s)*256+n)*256+c ; n:[0,64)=q(norm) [64,128)=k(norm)
// [128,192)=vH [192,256)=vV
__device__ __half g_Ph[134217728];
__device__ __half g_AHm[4194304];   // [bh][s][t]
__device__ __half g_AVm[4194304];
__device__ __half g_Wh[16384];      // qkv_w fp16 [256][64]
__device__ __half g_PWh[4096];      // proj_w fp16 [64][64]

#define DINL __device__ __forceinline__

DINL uint32_t su32(const void* p) { return (uint32_t)__cvta_generic_to_shared(p); }

DINL void ldsm4(uint32_t r[4], const void* p) {
    asm volatile("ldmatrix.sync.aligned.m8n8.x4.shared.b16 {%0,%1,%2,%3},[%4];"
        : "=r"(r[0]), "=r"(r[1]), "=r"(r[2]), "=r"(r[3]) : "r"(su32(p)));
}
DINL void ldsm4t(uint32_t r[4], const void* p) {
    asm volatile("ldmatrix.sync.aligned.m8n8.x4.trans.shared.b16 {%0,%1,%2,%3},[%4];"
        : "=r"(r[0]), "=r"(r[1]), "=r"(r[2]), "=r"(r[3]) : "r"(su32(p)));
}
DINL void mma8(float c[4], const uint32_t a[4], uint32_t b0, uint32_t b1) {
    asm volatile("mma.sync.aligned.m16n8k16.row.col.f32.f16.f16.f32 "
        "{%0,%1,%2,%3},{%4,%5,%6,%7},{%8,%9},{%0,%1,%2,%3};"
        : "+f"(c[0]), "+f"(c[1]), "+f"(c[2]), "+f"(c[3])
        : "r"(a[0]), "r"(a[1]), "r"(a[2]), "r"(a[3]), "r"(b0), "r"(b1));
}
DINL void cpa16(void* s, const void* g) {
    asm volatile("cp.async.cg.shared.global [%0], [%1], 16;" :: "r"(su32(s)), "l"(g));
}
DINL void cpcommit() { asm volatile("cp.async.commit_group;"); }
DINL void cpwait0()  { asm volatile("cp.async.wait_group 0;"); }
DINL void cpwait1()  { asm volatile("cp.async.wait_group 1;"); }

// ---------------------------------------------------------------------------
// Kernel 0: one-time fp32 -> fp16 weight conversion.
// ---------------------------------------------------------------------------
__global__ void k_cvt(const float* __restrict__ qkv_w, const float* __restrict__ proj_w)
{
    int t = blockIdx.x * 256 + threadIdx.x;     // 64 blocks x 256 = 16384
    if (t < 16384) g_Wh[t]  = __float2half_rn(qkv_w[t]);
    if (t < 4096)  g_PWh[t] = __float2half_rn(proj_w[t]);
}

// ---------------------------------------------------------------------------
// Kernel 1: P = X @ W^T + bias (per (b,s): 256x256, K=64), fused q/k 8-row-
// group L2 norm. grid(2048,2). 512 thr = 16 warps (4x4), warp tile 32x64.
// Epilogue: staged smem -> coalesced 64B-chunk global stores.
// ---------------------------------------------------------------------------
__global__ void __launch_bounds__(512, 1)
k_qkv(const float* __restrict__ x, const float* __restrict__ bias_)
{
    extern __shared__ __half sm[];
    __half* Xs = sm;                       // [128][72]
    __half* Ws = sm + 128 * 72;            // [256][72]
    __half* St = sm;                       // stage, reuse: [128][288]
    float*  bsh = (float*)((char*)sm + 73728);  // [256]
    float*  gss = bsh + 256;                    // [16]

    const int bs = blockIdx.x, half_ = blockIdx.y, n0 = half_ << 7;
    const int tid = threadIdx.x, lane = tid & 31, warp = tid >> 5;
    const int wr = warp >> 2, wc = warp & 3;

    { // X tile (128 x 64 fp32) -> fp16 smem
        int row = tid >> 2, k0 = (tid & 3) << 4;
        const float* src = x + ((size_t)bs * 256 + n0 + row) * 64 + k0;
        __half* dst = Xs + row * 72 + k0;
        #pragma unroll
        for (int i = 0; i < 4; i++) {
            float4 v = *(const float4*)(src + i * 4);
            dst[i*4+0] = __float2half_rn(v.x); dst[i*4+1] = __float2half_rn(v.y);
            dst[i*4+2] = __float2half_rn(v.z); dst[i*4+3] = __float2half_rn(v.w);
        }
    }
    { // W fp16 via cp.async: 2048 16B segs / 512 thr = 4 each
        #pragma unroll
        for (int i = 0; i < 4; i++) {
            int seg = tid * 4 + i;
            int row = seg >> 3, off = (seg & 7) << 3;
            cpa16(Ws + row * 72 + off, g_Wh + row * 64 + off);
        }
        cpcommit();
    }
    if (tid < 256) bsh[tid] = bias_[tid];
    if (tid < 16)  gss[tid] = 0.f;
    cpwait0();
    __syncthreads();

    float acc[2][8][4];
    #pragma unroll
    for (int mt = 0; mt < 2; mt++)
        #pragma unroll
        for (int nt = 0; nt < 8; nt++)
            #pragma unroll
            for (int q = 0; q < 4; q++) acc[mt][nt][q] = 0.f;

    #pragma unroll
    for (int kk = 0; kk < 4; kk++) {
        uint32_t af[2][4];
        #pragma unroll
        for (int mt = 0; mt < 2; mt++)
            ldsm4(af[mt], Xs + (wr*32 + mt*16 + (lane & 15)) * 72
                             + kk*16 + ((lane >> 4) << 3));
        #pragma unroll
        for (int g = 0; g < 4; g++) {
            uint32_t r[4];
            ldsm4(r, Ws + (wc*64 + g*16 + (lane & 15)) * 72
                        + kk*16 + ((lane >> 4) << 3));
            #pragma unroll
            for (int mt = 0; mt < 2; mt++) {
                mma8(acc[mt][2*g],   af[mt], r[0], r[2]);
                mma8(acc[mt][2*g+1], af[mt], r[1], r[3]);
            }
        }
    }

    // bias before norm
    #pragma unroll
    for (int nt = 0; nt < 8; nt++) {
        float b0 = bsh[wc*64 + nt*8 + 2*(lane & 3)];
        float b1 = bsh[wc*64 + nt*8 + 2*(lane & 3) + 1];
        #pragma unroll
        for (int mt = 0; mt < 2; mt++) {
            acc[mt][nt][0] += b0; acc[mt][nt][1] += b1;
            acc[mt][nt][2] += b0; acc[mt][nt][3] += b1;
        }
    }

    // q/k 8-row-group norms (half 0 only)
    if (half_ == 0) {
        #pragma unroll
        for (int mt = 0; mt < 2; mt++) {
            float p01 = 0.f, p23 = 0.f;
            #pragma unroll
            for (int nt = 0; nt < 8; nt++) {
                p01 += acc[mt][nt][0]*acc[mt][nt][0] + acc[mt][nt][1]*acc[mt][nt][1];
                p23 += acc[mt][nt][2]*acc[mt][nt][2] + acc[mt][nt][3]*acc[mt][nt][3];
            }
            #pragma unroll
            for (int off = 16; off > 0; off >>= 1) {
                p01 += __shfl_xor_sync(0xffffffffu, p01, off);
                p23 += __shfl_xor_sync(0xffffffffu, p23, off);
            }
            if (lane == 0) {
                atomicAdd(&gss[wr*4 + mt*2],     p01);
                atomicAdd(&gss[wr*4 + mt*2 + 1], p23);
            }
        }
    }
    __syncthreads();

    // stage scaled fp16 fragments into smem
    // layout: row stride 288 halves; 16B unit swizzle u ^= (row>>1)&1
    #pragma unroll
    for (int mt = 0; mt < 2; mt++) {
        float s01 = 1.f, s23 = 1.f;
        if (half_ == 0) {
            s01 = 1.f / fmaxf(sqrtf(gss[wr*4 + mt*2]),     1e-12f);
            s23 = 1.f / fmaxf(sqrtf(gss[wr*4 + mt*2 + 1]), 1e-12f);
        }
        int r0 = wr*32 + mt*16 + (lane >> 2);
        int xr = (r0 >> 1) & 1;                       // same for r0 and r0+8
        #pragma unroll
        for (int nt = 0; nt < 8; nt++) {
            int c = wc*64 + nt*8 + 2*(lane & 3);
            int u = c >> 3, sub = c & 7;
            int up = ((u ^ xr) << 3) + sub;
            *(__half2*)(St + r0*288 + up) =
                __floats2half2_rn(acc[mt][nt][0]*s01, acc[mt][nt][1]*s01);
            *(__half2*)(St + (r0+8)*288 + up) =
                __floats2half2_rn(acc[mt][nt][2]*s23, acc[mt][nt][3]*s23);
        }
    }
    __syncthreads();

    // coalesced global store: thread (row = tid>>2, q = tid&3), 8 x 16B
    {
        int row = tid >> 2, q = tid & 3;
        int xr = (row >> 1) & 1;
        const __half* base = St + row * 288;
        __half* gp = g_Ph + ((size_t)bs * 256 + n0 + row) * 256;
        #pragma unroll
        for (int i = 0; i < 8; i++) {
            int u = q + 4*i;
            uint4 v = *(const uint4*)(base + ((u ^ xr) << 3));
            *(uint4*)(gp + (u << 3)) = v;
        }
    }
}

// ---------------------------------------------------------------------------
// Kernel 2: sim = Qn @ Kn^T per (b,h) + dual softmax (no max-shift; |sim|<=1).
// grid(64,2). 512 thr, warp tile 32x64 over 128x256. K=2048, chunk 64,
// cp.async double buffered.
// ---------------------------------------------------------------------------
__global__ void __launch_bounds__(512, 1)
k_attn(const float* __restrict__ t1g, const float* __restrict__ t2g)
{
    extern __shared__ __half sm2[];
    __half* Qs = sm2;                       // 2 x [128][88]
    __half* Ks = sm2 + 2 * 128 * 88;        // 2 x [256][88]
    float*  rs1 = (float*)(Ks + 2 * 256 * 88); // [128]
    float*  rs2 = rs1 + 128;                   // [128]

    const int bh = blockIdx.x, s0 = blockIdx.y << 7;
    const int b = bh >> 3, h = bh & 7;
    const __half* qb = g_Ph + (size_t)b * 16777216 + h * 2048;
    const __half* kb = qb + 16384;

    const int tid = threadIdx.x, lane = tid & 31, warp = tid >> 5;
    const int wr = warp >> 2, wc = warp & 3;

    if (tid < 128) { rs1[tid] = 0.f; rs2[tid] = 0.f; }

    auto loadQ = [&](int buf, int c) {
        int d0 = c * 64;
        #pragma unroll
        for (int i = 0; i < 2; i++) {
            int seg = tid * 2 + i, row = seg >> 3, off = (seg & 7) << 3;
            cpa16(Qs + buf*11264 + row*88 + off,
                  qb + (size_t)(s0 + row) * 65536 + d0 + off);
        }
    };
    auto loadK = [&](int buf, int c) {
        int d0 = c * 64;
        #pragma unroll
        for (int i = 0; i < 4; i++) {
            int seg = tid * 4 + i, row = seg >> 3, off = (seg & 7) << 3;
            cpa16(Ks + buf*22528 + row*88 + off,
                  kb + (size_t)row * 65536 + d0 + off);
        }
    };

    float acc[2][8][4];
    #pragma unroll
    for (int mt = 0; mt < 2; mt++)
        #pragma unroll
        for (int nt = 0; nt < 8; nt++)
            #pragma unroll
            for (int q = 0; q < 4; q++) acc[mt][nt][q] = 0.f;

    loadQ(0, 0); loadK(0, 0); cpcommit();
    for (int c = 0; c < 32; c++) {
        if (c < 31) { loadQ((c+1)&1, c+1); loadK((c+1)&1, c+1); cpcommit(); cpwait1(); }
        else cpwait0();
        __syncthreads();
        const __half* Q = Qs + (c & 1) * 11264;
        const __half* K = Ks + (c & 1) * 22528;
        #pragma unroll
        for (int kk = 0; kk < 4; kk++) {
            uint32_t af[2][4];
            #pragma unroll
            for (int mt = 0; mt < 2; mt++)
                ldsm4(af[mt], Q + (wr*32 + mt*16 + (lane & 15)) * 88
                                + kk*16 + ((lane >> 4) << 3));
            #pragma unroll
            for (int g = 0; g < 4; g++) {
                uint32_t r[4];
                ldsm4(r, K + (wc*64 + g*16 + (lane & 15)) * 88
                           + kk*16 + ((lane >> 4) << 3));
                #pragma unroll
                for (int mt = 0; mt < 2; mt++) {
                    mma8(acc[mt][2*g],   af[mt], r[0], r[2]);
                    mma8(acc[mt][2*g+1], af[mt], r[1], r[3]);
                }
            }
        }
        __syncthreads();
    }

    const float t1 = t1g[h], t2 = t2g[h];

    // pass 1: row sums of exp
    #pragma unroll
    for (int mt = 0; mt < 2; mt++) {
        float p1a = 0.f, p1b = 0.f, p2a = 0.f, p2b = 0.f;
        #pragma unroll
        for (int nt = 0; nt < 8; nt++) {
            p1a += __expf(acc[mt][nt][0]*t1) + __expf(acc[mt][nt][1]*t1);
            p1b += __expf(acc[mt][nt][2]*t1) + __expf(acc[mt][nt][3]*t1);
            p2a += __expf(acc[mt][nt][0]*t2) + __expf(acc[mt][nt][1]*t2);
            p2b += __expf(acc[mt][nt][2]*t2) + __expf(acc[mt][nt][3]*t2);
        }
        #pragma unroll
        for (int off = 1; off < 4; off <<= 1) {
            p1a += __shfl_xor_sync(0xffffffffu, p1a, off);
            p1b += __shfl_xor_sync(0xffffffffu, p1b, off);
            p2a += __shfl_xor_sync(0xffffffffu, p2a, off);
            p2b += __shfl_xor_sync(0xffffffffu, p2b, off);
        }
        if ((lane & 3) == 0) {
            int r0 = wr*32 + mt*16 + (lane >> 2);
            atomicAdd(&rs1[r0], p1a);     atomicAdd(&rs1[r0 + 8], p1b);
            atomicAdd(&rs2[r0], p2a);     atomicAdd(&rs2[r0 + 8], p2b);
        }
    }
    __syncthreads();

    // pass 2: normalize + store fp16
    #pragma unroll
    for (int mt = 0; mt < 2; mt++) {
        int r0 = wr*32 + mt*16 + (lane >> 2);
        float i1a = 1.f / rs1[r0], i1b = 1.f / rs1[r0 + 8];
        float i2a = 1.f / rs2[r0], i2b = 1.f / rs2[r0 + 8];
        #pragma unroll
        for (int nt = 0; nt < 8; nt++) {
            int col = wc*64 + nt*8 + 2*(lane & 3);
            size_t base = (size_t)bh * 65536 + (size_t)(s0 + r0) * 256 + col;
            *(__half2*)(g_AHm + base) = __floats2half2_rn(
                __expf(acc[mt][nt][0]*t1)*i1a, __expf(acc[mt][nt][1]*t1)*i1a);
            *(__half2*)(g_AHm + base + 2048) = __floats2half2_rn(
                __expf(acc[mt][nt][2]*t1)*i1b, __expf(acc[mt][nt][3]*t1)*i1b);
            *(__half2*)(g_AVm + base) = __floats2half2_rn(
                __expf(acc[mt][nt][0]*t2)*i2a, __expf(acc[mt][nt][1]*t2)*i2a);
            *(__half2*)(g_AVm + base + 2048) = __floats2half2_rn(
                __expf(acc[mt][nt][2]*t2)*i2b, __expf(acc[mt][nt][3]*t2)*i2b);
        }
    }
}

// ---------------------------------------------------------------------------
// Kernel 3: xsum = A_H@V_H + A_V@V_Vfinal per (b,h) [128s x 256d block],
// fused proj MMA epilogue -> out. grid(64,16), 512 thr, warp 32x64.
// K=256 (t), chunk 32, cp.async double buffered. V via ldmatrix.trans.
// ---------------------------------------------------------------------------
__global__ void __launch_bounds__(512, 1)
k_av(const float* __restrict__ pb, float* __restrict__ out)
{
    extern __shared__ __half sm3[];
    __half* AHs = sm3;                   // 2 x [128][40]
    __half* AVs = AHs + 2 * 5120;        // 2 x [128][40]
    __half* Vhs = AVs + 2 * 5120;        // 2 x [32][264]
    __half* Vvs = Vhs + 2 * 8448;        // 2 x [32][264]
    __half* PWs = Vvs + 2 * 8448;        // [64][72]
    float*  pbs = (float*)(PWs + 64 * 72); // [64]
    __half* XSs = sm3;                   // reuse: [128][264]

    const int bh = blockIdx.x, b = bh >> 3, h = bh & 7;
    const int tile = blockIdx.y;
    const int s0 = (tile & 1) << 7, dg = tile >> 1;
    const int d0 = dg << 8, j0 = dg << 2;

    const int tid = threadIdx.x, lane = tid & 31, warp = tid >> 5;
    const int wr = warp >> 2, wc = warp & 3;

    const __half* AHg = g_AHm + (size_t)bh * 65536 + (size_t)s0 * 256;
    const __half* AVg = g_AVm + (size_t)bh * 65536 + (size_t)s0 * 256;
    const __half* vh  = g_Ph + (size_t)b * 16777216 + 32768 + h * 2048 + d0;
    const __half* vv  = g_Ph + (size_t)b * 16777216 + (size_t)(h*32 + j0) * 65536 + 49152;

    { // proj weight fp16 via cp.async: 512 segs / 512 thr
        int row = tid >> 3, off = (tid & 7) << 3;
        cpa16(PWs + row * 72 + off, g_PWh + row * 64 + off);
    }
    if (tid < 64) pbs[tid] = pb[tid];

    auto loadA = [&](int buf, int c) {
        int t0 = c * 32;
        int row = tid >> 2, off = (tid & 3) << 3;
        cpa16(AHs + buf*5120 + row*40 + off, AHg + (size_t)row * 256 + t0 + off);
        cpa16(AVs + buf*5120 + row*40 + off, AVg + (size_t)row * 256 + t0 + off);
    };
    auto loadV = [&](int buf, int c) {
        int t0 = c * 32;
        #pragma unroll
        for (int i = 0; i < 2; i++) {
            int sg = tid * 2 + i, row = sg >> 5, off = (sg & 31) << 3;
            cpa16(Vhs + buf*8448 + row*264 + off,
                  vh + (size_t)(t0 + row) * 65536 + off);
            int jj = off >> 6, cc = off & 63;
            cpa16(Vvs + buf*8448 + row*264 + off,
                  vv + (size_t)jj * 65536 + (t0 + row) * 64 + cc);
        }
    };

    float acc[2][8][4];
    #pragma unroll
    for (int mt = 0; mt < 2; mt++)
        #pragma unroll
        for (int nt = 0; nt < 8; nt++)
            #pragma unroll
            for (int q = 0; q < 4; q++) acc[mt][nt][q] = 0.f;

    loadA(0, 0); loadV(0, 0); cpcommit();
    for (int c = 0; c < 8; c++) {
        if (c < 7) { loadA((c+1)&1, c+1); loadV((c+1)&1, c+1); cpcommit(); cpwait1(); }
        else cpwait0();
        __syncthreads();
        const __half* AH = AHs + (c & 1) * 5120;
        const __half* AV = AVs + (c & 1) * 5120;
        const __half* VH = Vhs + (c & 1) * 8448;
        const __half* VV = Vvs + (c & 1) * 8448;
        #pragma unroll
        for (int kk = 0; kk < 2; kk++) {
            uint32_t aH[2][4], aV[2][4];
            #pragma unroll
            for (int mt = 0; mt < 2; mt++) {
                ldsm4(aH[mt], AH + (wr*32 + mt*16 + (lane & 15)) * 40
                                 + kk*16 + ((lane >> 4) << 3));
                ldsm4(aV[mt], AV + (wr*32 + mt*16 + (lane & 15)) * 40
                                 + kk*16 + ((lane >> 4) << 3));
            }
            #pragma unroll
            for (int g = 0; g < 4; g++) {
                int D0 = wc*64 + g*16;
                int trow = kk*16 + ((lane >> 4) << 3) + (lane & 7);
                int dcol = D0 + (((lane >> 3) & 1) << 3);
                uint32_t r[4];
                ldsm4t(r, VH + trow*264 + dcol);
                #pragma unroll
                for (int mt = 0; mt < 2; mt++) {
                    mma8(acc[mt][2*g],   aH[mt], r[0], r[2]);
                    mma8(acc[mt][2*g+1], aH[mt], r[1], r[3]);
                }
                ldsm4t(r, VV + trow*264 + dcol);
                #pragma unroll
                for (int mt = 0; mt < 2; mt++) {
                    mma8(acc[mt][2*g],   aV[mt], r[0], r[2]);
                    mma8(acc[mt][2*g+1], aV[mt], r[1], r[3]);
                }
            }
        }
        __syncthreads();
    }

    // stage xsum fp16 -> smem, then proj MMA
    __syncthreads();
    #pragma unroll
    for (int mt = 0; mt < 2; mt++) {
        int r0 = wr*32 + mt*16 + (lane >> 2);
        #pragma unroll
        for (int nt = 0; nt < 8; nt++) {
            int col = wc*64 + nt*8 + 2*(lane & 3);
            *(__half2*)(XSs + r0*264 + col) =
                __floats2half2_rn(acc[mt][nt][0], acc[mt][nt][1]);
            *(__half2*)(XSs + (r0+8)*264 + col) =
                __floats2half2_rn(acc[mt][nt][2], acc[mt][nt][3]);
        }
    }
    __syncthreads();

    float a2[2][8][4];
    #pragma unroll
    for (int mt = 0; mt < 2; mt++)
        #pragma unroll
        for (int nt = 0; nt < 8; nt++)
            #pragma unroll
            for (int q = 0; q < 4; q++) a2[mt][nt][q] = 0.f;

    #pragma unroll
    for (int kk = 0; kk < 4; kk++) {
        uint32_t af[2][4];
        #pragma unroll
        for (int mt = 0; mt < 2; mt++)
            ldsm4(af[mt], XSs + (wr*32 + mt*16 + (lane & 15)) * 264
                              + wc*64 + kk*16 + ((lane >> 4) << 3));
        #pragma unroll
        for (int g = 0; g < 4; g++) {
            uint32_t r[4];
            ldsm4(r, PWs + (g*16 + (lane & 15)) * 72
                         + kk*16 + ((lane >> 4) << 3));
            #pragma unroll
            for (int mt = 0; mt < 2; mt++) {
                mma8(a2[mt][2*g],   af[mt], r[0], r[2]);
                mma8(a2[mt][2*g+1], af[mt], r[1], r[3]);
            }
        }
    }

    #pragma unroll
    for (int mt = 0; mt < 2; mt++) {
        int r0 = wr*32 + mt*16 + (lane >> 2);
        #pragma unroll
        for (int nt = 0; nt < 8; nt++) {
            int co = nt*8 + 2*(lane & 3);
            float b0 = pbs[co], b1 = pbs[co + 1];
            float* o0 = out + ((size_t)(b*256 + s0 + r0) * 256 + h*32 + j0 + wc) * 64 + co;
            float* o1 = out + ((size_t)(b*256 + s0 + r0 + 8) * 256 + h*32 + j0 + wc) * 64 + co;
            *(float2*)o0 = make_float2(a2[mt][nt][0] + b0, a2[mt][nt][1] + b1);
            *(float2*)o1 = make_float2(a2[mt][nt][2] + b0, a2[mt][nt][3] + b1);
        }
    }
}

// ---------------------------------------------------------------------------
extern "C" void kernel_launch(void* const* d_in, const int* in_sizes, int n_in,
                              void* d_out, int out_size)
{
    const float* x      = (const float*)d_in[0];
    const float* qkv_w  = (const float*)d_in[1];
    const float* qkv_b  = (const float*)d_in[2];
    const float* proj_w = (const float*)d_in[3];
    const float* proj_b = (const float*)d_in[4];
    const float* t1     = (const float*)d_in[5];
    const float* t2     = (const float*)d_in[6];
    float* out = (float*)d_out;

    const int smem1 = 73728 + 256*4 + 64;                              // ~74.8 KB
    const int smem2 = (2*128*88 + 2*256*88) * 2 + 256 * 4;             // ~136.2 KB
    const int smem3 = (2*5120*2 + 2*8448*2 + 64*72) * 2 + 64 * 4;      // ~118.0 KB

    cudaFuncSetAttribute((const void*)k_qkv,
                         cudaFuncAttributeMaxDynamicSharedMemorySize, smem1);
    cudaFuncSetAttribute((const void*)k_attn,
                         cudaFuncAttributeMaxDynamicSharedMemorySize, smem2);
    cudaFuncSetAttribute((const void*)k_av,
                         cudaFuncAttributeMaxDynamicSharedMemorySize, smem3);

    k_cvt <<<64, 256>>>(qkv_w, proj_w);
    k_qkv <<<dim3(2048, 2), 512, smem1>>>(x, qkv_b);
    k_attn<<<dim3(64, 2),   512, smem2>>>(t1, t2);
    k_av  <<<dim3(64, 16),  512, smem3>>>(proj_b, out);
}